// round 16
// baseline (speedup 1.0000x reference)
#include <cuda_runtime.h>

typedef unsigned long long ull;
#define DEVFN __device__ __forceinline__

#define TT 32
#define BB 2048
#define DD 64
#define MT 16
#define NTH 512
#define NCTA (BB / MT)
#define HP 20

// smem layout (float offsets)
#define OFF_W0T 0                        // [64][256]
#define OFF_B0  (OFF_W0T + 64*256)       // 16384
#define OFF_B1  (OFF_B0 + 256)
#define OFF_B2  (OFF_B1 + 256)
#define OFF_TS  (OFF_B2 + 64)
#define OFF_Y   (OFF_TS + 32)            // [64][HP]
#define OFF_YT  (OFF_Y + 64*HP)
#define OFF_K   (OFF_YT + 64*HP)         // [5][128][8]
#define OFF_H0  (OFF_K + 5*128*8)        // [256][HP]
#define OFF_H1  (OFF_H0 + 256*HP)        // [256][HP]
#define OFF_SCR (OFF_H1 + 256*HP)        // 16384 floats
#define SMEM_FLOATS (OFF_SCR + 16384)    // 51296
#define SMEM_BYTES (SMEM_FLOATS * 4)     // 205184 (<= 232448)

__device__ float g_W1T[(256 + 16) * 256];  // [k][w]
__device__ float g_W2T[(256 + 16) * 64];   // [u][d]

__constant__ float c_A[30] = {
    0.f, 0.f, 0.f, 0.f, 0.f,
    0.2f, 0.f, 0.f, 0.f, 0.f,
    (float)(3.0/40.0), (float)(9.0/40.0), 0.f, 0.f, 0.f,
    (float)(44.0/45.0), (float)(-56.0/15.0), (float)(32.0/9.0), 0.f, 0.f,
    (float)(19372.0/6561.0), (float)(-25360.0/2187.0), (float)(64448.0/6561.0), (float)(-212.0/729.0), 0.f,
    (float)(9017.0/3168.0), (float)(-355.0/33.0), (float)(46732.0/5247.0), (float)(49.0/176.0), (float)(-5103.0/18656.0)
};
__constant__ float c_C6[6] = {0.f, 0.2f, 0.3f, 0.8f, (float)(8.0/9.0), 1.f};
__constant__ float c_B6[6] = {(float)(35.0/384.0), 0.f, (float)(500.0/1113.0),
                              (float)(125.0/192.0), (float)(-2187.0/6784.0), (float)(11.0/84.0)};

DEVFN ull dup2(float x) {
    ull r; unsigned xi = __float_as_uint(x);
    asm("mov.b64 %0, {%1, %1};" : "=l"(r) : "r"(xi));
    return r;
}
DEVFN void fma2(ull& d, ull a, ull b) {
    asm("fma.rn.f32x2 %0, %1, %2, %0;" : "+l"(d) : "l"(a), "l"(b));
}
DEVFN ull addx2(ull a, ull b) {
    ull r;
    asm("add.rn.f32x2 %0, %1, %2;" : "=l"(r) : "l"(a), "l"(b));
    return r;
}
DEVFN void unpk(ull v, float& lo, float& hi) {
    unsigned a, b;
    asm("mov.b64 {%0, %1}, %2;" : "=r"(a), "=r"(b) : "l"(v));
    lo = __uint_as_float(a); hi = __uint_as_float(b);
}
DEVFN float fast_tanh(float x) {
    float ax = fabsf(x);
    float e  = __expf(-2.0f * ax);
    float r  = __fdividef(1.0f - e, 1.0f + e);
    return copysignf(r, x);
}

DEVFN void col4(ull* acc, ull bb, const ulonglong2& a01, const ulonglong2& a23) {
    fma2(acc[0], a01.x, bb); fma2(acc[1], a01.y, bb);
    fma2(acc[2], a23.x, bb); fma2(acc[3], a23.y, bb);
}

// one dopri5 stage s: k_{s+1} + tableau folded into GEMM2 epilogue
DEVFN void vf_eval(float* sm, int s, float h, float tstage, const float* aIn, int tid) {
    float* scr = sm + OFF_SCR;

    int grp = tid >> 7;                   // 0..3 (warp-uniform)
    int t1  = tid & 127;
    int cg = t1 >> 1, rh1 = t1 & 1;       // GEMM1 producer: col-quad, row-half
    int c1 = 4 * cg, rb1 = 8 * rh1;
    int rh2 = t1 >> 6, d2 = t1 & 63;      // GEMM2: row-half, col
    int rb2 = 8 * rh2;
    int t4 = t1 * 4;

    // hoisted B prefetches (L2 latency hides behind GEMM0)
    const float* pb1 = g_W1T + grp * 256 + c1;
    float4 bbuf[4];
#pragma unroll
    for (int jj = 0; jj < 4; ++jj)
        bbuf[jj] = *reinterpret_cast<const float4*>(pb1 + jj * 1024);
    const float* pb2 = g_W2T + grp * 64 + d2;
    float bw[4];
#pragma unroll
    for (int jj = 0; jj < 4; ++jj)
        bw[jj] = pb2[jj * 256];

    // ---- GEMM0 produce: kh=tid>>8; col-pair cp x row-half rh; all threads store ----
    {
        int kh = tid >> 8, t = tid & 255;
        int cp = t & 127, rh = t >> 7;
        int c0 = 2 * cp, rb = 8 * rh;
        ull acc[8];
#pragma unroll
        for (int p = 0; p < 8; ++p) acc[p] = 0ull;
        const float* pa = aIn + rb;
        const float* pb = sm + OFF_W0T + c0;
#pragma unroll 4
        for (int j = 0; j < 32; ++j) {
            int k = 2 * j + kh;
            float2 b2 = *reinterpret_cast<const float2*>(pb + k * 256);
            ulonglong2 a01 = *reinterpret_cast<const ulonglong2*>(pa + k * HP);
            ulonglong2 a23 = *reinterpret_cast<const ulonglong2*>(pa + k * HP + 4);
            col4(acc,     dup2(b2.x), a01, a23);
            col4(acc + 4, dup2(b2.y), a01, a23);
        }
        // piece p: col c0+(p>>1), rows 4(p&1)+rb..; layout scr[kh*4096 + p*1024 + t*4]
#pragma unroll
        for (int p = 0; p < 4; ++p) {
            ulonglong2 w; w.x = acc[2 * p]; w.y = acc[2 * p + 1];
            *reinterpret_cast<ulonglong2*>(scr + kh * 4096 + p * 1024 + t * 4) = w;
        }
    }
    __syncthreads();                                   // S1

    // ---- GEMM0 reduce+tanh: each thread owns col w=2(t&127)+a, rows 8(t>>7).. ----
    {
        int a = tid >> 8, t = tid & 255;
        int w = 2 * (t & 127) + a;
        int rb = 8 * (t >> 7);
        ulonglong2 q00 = *reinterpret_cast<const ulonglong2*>(scr + (2 * a) * 1024 + t * 4);
        ulonglong2 q01 = *reinterpret_cast<const ulonglong2*>(scr + (2 * a + 1) * 1024 + t * 4);
        ulonglong2 q10 = *reinterpret_cast<const ulonglong2*>(scr + 4096 + (2 * a) * 1024 + t * 4);
        ulonglong2 q11 = *reinterpret_cast<const ulonglong2*>(scr + 4096 + (2 * a + 1) * 1024 + t * 4);
        ull s0 = addx2(q00.x, q10.x), s1 = addx2(q00.y, q10.y);
        ull s2 = addx2(q01.x, q11.x), s3 = addx2(q01.y, q11.y);
        float bj = sm[OFF_B0 + w];
        float v[8];
        unpk(s0, v[0], v[1]); unpk(s1, v[2], v[3]);
        unpk(s2, v[4], v[5]); unpk(s3, v[6], v[7]);
#pragma unroll
        for (int i = 0; i < 8; ++i) v[i] = fast_tanh(v[i] + bj);
        float* hp = sm + OFF_H0 + w * HP + rb;
        *reinterpret_cast<float4*>(hp)     = make_float4(v[0], v[1], v[2], v[3]);
        *reinterpret_cast<float4*>(hp + 4) = make_float4(v[4], v[5], v[6], v[7]);
    }
    __syncthreads();                                   // S2

    // ---- GEMM1 produce: 4-way k-split (grp); col-quad x row-half; all grps store ----
    {
        ull acc[16];
#pragma unroll
        for (int p = 0; p < 16; ++p) acc[p] = 0ull;
        const float* pa = sm + OFF_H0 + rb1;
#pragma unroll 4
        for (int j = 0; j < 64; ++j) {
            float4 b4 = bbuf[j & 3];
            bbuf[j & 3] = *reinterpret_cast<const float4*>(pb1 + (j + 4) * 1024);
            int k = 4 * j + grp;
            ulonglong2 a01 = *reinterpret_cast<const ulonglong2*>(pa + k * HP);
            ulonglong2 a23 = *reinterpret_cast<const ulonglong2*>(pa + k * HP + 4);
            col4(acc,      dup2(b4.x), a01, a23);
            col4(acc + 4,  dup2(b4.y), a01, a23);
            col4(acc + 8,  dup2(b4.z), a01, a23);
            col4(acc + 12, dup2(b4.w), a01, a23);
        }
        // piece p: col c1+(p>>1), rows 4(p&1)+rb1; layout scr[grp*4096 + p*512 + t1*4]
#pragma unroll
        for (int p = 0; p < 8; ++p) {
            ulonglong2 w; w.x = acc[2 * p]; w.y = acc[2 * p + 1];
            *reinterpret_cast<ulonglong2*>(scr + grp * 4096 + p * 512 + t4) = w;
        }
    }
    __syncthreads();                                   // S3

    // ---- GEMM1 reduce+tanh: thread (a=grp, t1) owns col 4(t1>>1)+a, rows 8(t1&1).. ----
    {
        int a = grp;
        int w = 4 * (t1 >> 1) + a;
        int rb = 8 * (t1 & 1);
        ull s0 = 0ull, s1 = 0ull, s2 = 0ull, s3 = 0ull;
#pragma unroll
        for (int g = 0; g < 4; ++g) {
            ulonglong2 q0 = *reinterpret_cast<const ulonglong2*>(scr + g * 4096 + (2 * a) * 512 + t4);
            ulonglong2 q1 = *reinterpret_cast<const ulonglong2*>(scr + g * 4096 + (2 * a + 1) * 512 + t4);
            s0 = addx2(s0, q0.x); s1 = addx2(s1, q0.y);
            s2 = addx2(s2, q1.x); s3 = addx2(s3, q1.y);
        }
        float bj = sm[OFF_B1 + w];
        float v[8];
        unpk(s0, v[0], v[1]); unpk(s1, v[2], v[3]);
        unpk(s2, v[4], v[5]); unpk(s3, v[6], v[7]);
#pragma unroll
        for (int i = 0; i < 8; ++i) v[i] = fast_tanh(v[i] + bj);
        float* hp = sm + OFF_H1 + w * HP + rb;
        *reinterpret_cast<float4*>(hp)     = make_float4(v[0], v[1], v[2], v[3]);
        *reinterpret_cast<float4*>(hp + 4) = make_float4(v[4], v[5], v[6], v[7]);
    }
    __syncthreads();                                   // S4

    // ---- GEMM2: 4-way u-split (grp); col d x row-half; tableau folded into epilogue ----
    {
        ull acc2[4];
#pragma unroll
        for (int p = 0; p < 4; ++p) acc2[p] = 0ull;
        const float* pa = sm + OFF_H1 + rb2;
#pragma unroll 4
        for (int j = 0; j < 64; ++j) {
            float b = bw[j & 3];
            bw[j & 3] = pb2[(j + 4) * 256];
            int u = 4 * j + grp;
            ull bb = dup2(b);
            ulonglong2 a01 = *reinterpret_cast<const ulonglong2*>(pa + u * HP);
            ulonglong2 a23 = *reinterpret_cast<const ulonglong2*>(pa + u * HP + 4);
            col4(acc2, bb, a01, a23);
        }
        if (grp) {
#pragma unroll
            for (int p = 0; p < 2; ++p) {
                ulonglong2 w; w.x = acc2[2 * p]; w.y = acc2[2 * p + 1];
                *reinterpret_cast<ulonglong2*>(scr + (grp - 1) * 1024 + p * 512 + t4) = w;
            }
        }
        __syncthreads();                               // S5
        if (grp == 0) {
#pragma unroll
            for (int pc = 0; pc < 3; ++pc)
#pragma unroll
                for (int p = 0; p < 2; ++p) {
                    ulonglong2 q = *reinterpret_cast<const ulonglong2*>(scr + pc * 1024 + p * 512 + t4);
                    acc2[2 * p]     = addx2(acc2[2 * p], q.x);
                    acc2[2 * p + 1] = addx2(acc2[2 * p + 1], q.y);
                }
            float et = expf(tstage);
            float bd = sm[OFF_B2 + d2];
            float v[8];
#pragma unroll
            for (int p = 0; p < 4; ++p) unpk(acc2[p], v[2 * p], v[2 * p + 1]);
#pragma unroll
            for (int i = 0; i < 8; ++i) v[i] = (v[i] + bd) * et;   // k_{s+1}

            float* kb = sm + OFF_K + t1 * 8;
            const float* yp = sm + OFF_Y + d2 * HP + rb2;
            float4 ya = *reinterpret_cast<const float4*>(yp);
            float4 yb = *reinterpret_cast<const float4*>(yp + 4);
            float yv[8] = {ya.x, ya.y, ya.z, ya.w, yb.x, yb.y, yb.z, yb.w};
            float ac[8];
            if (s < 5) {
                *reinterpret_cast<float4*>(kb + s * 1024)     = make_float4(v[0], v[1], v[2], v[3]);
                *reinterpret_cast<float4*>(kb + s * 1024 + 4) = make_float4(v[4], v[5], v[6], v[7]);
                float alast = c_A[(s + 1) * 5 + s];
#pragma unroll
                for (int i = 0; i < 8; ++i) ac[i] = alast * v[i];
                for (int j = 0; j < s; ++j) {
                    float aj = c_A[(s + 1) * 5 + j];
                    float4 ka = *reinterpret_cast<const float4*>(kb + j * 1024);
                    float4 kc = *reinterpret_cast<const float4*>(kb + j * 1024 + 4);
                    ac[0] += aj * ka.x; ac[1] += aj * ka.y; ac[2] += aj * ka.z; ac[3] += aj * ka.w;
                    ac[4] += aj * kc.x; ac[5] += aj * kc.y; ac[6] += aj * kc.z; ac[7] += aj * kc.w;
                }
                float* ytp = sm + OFF_YT + d2 * HP + rb2;
                *reinterpret_cast<float4*>(ytp)     = make_float4(yv[0] + h * ac[0], yv[1] + h * ac[1],
                                                                  yv[2] + h * ac[2], yv[3] + h * ac[3]);
                *reinterpret_cast<float4*>(ytp + 4) = make_float4(yv[4] + h * ac[4], yv[5] + h * ac[5],
                                                                  yv[6] + h * ac[6], yv[7] + h * ac[7]);
            } else {
#pragma unroll
                for (int i = 0; i < 8; ++i) ac[i] = c_B6[5] * v[i];
#pragma unroll
                for (int jj = 0; jj < 4; ++jj) {
                    const int jlist[4] = {0, 2, 3, 4};
                    int j = jlist[jj];
                    float aj = c_B6[j];
                    float4 ka = *reinterpret_cast<const float4*>(kb + j * 1024);
                    float4 kc = *reinterpret_cast<const float4*>(kb + j * 1024 + 4);
                    ac[0] += aj * ka.x; ac[1] += aj * ka.y; ac[2] += aj * ka.z; ac[3] += aj * ka.w;
                    ac[4] += aj * kc.x; ac[5] += aj * kc.y; ac[6] += aj * kc.z; ac[7] += aj * kc.w;
                }
                float* ypo = sm + OFF_Y + d2 * HP + rb2;
                *reinterpret_cast<float4*>(ypo)     = make_float4(yv[0] + h * ac[0], yv[1] + h * ac[1],
                                                                  yv[2] + h * ac[2], yv[3] + h * ac[3]);
                *reinterpret_cast<float4*>(ypo + 4) = make_float4(yv[4] + h * ac[4], yv[5] + h * ac[5],
                                                                  yv[6] + h * ac[6], yv[7] + h * ac[7]);
            }
        }
    }
    __syncthreads();                                   // S6
}

__global__ void __launch_bounds__(256, 1)
prep_kernel(const float* __restrict__ W1, const float* __restrict__ W2,
            const float* __restrict__ y0, float* __restrict__ out) {
    int stride = gridDim.x * blockDim.x;
    int t0 = blockIdx.x * blockDim.x + threadIdx.x;
    for (int idx = t0; idx < 256 * 256; idx += stride) {
        int r = idx >> 8, c = idx & 255;
        g_W1T[c * 256 + r] = W1[idx];
    }
    for (int idx = t0; idx < 16 * 256; idx += stride)
        g_W1T[65536 + idx] = 0.f;
    for (int idx = t0; idx < 64 * 256; idx += stride) {
        int d = idx >> 8, u = idx & 255;
        g_W2T[u * 64 + d] = W2[idx];
    }
    for (int idx = t0; idx < 16 * 64; idx += stride)
        g_W2T[16384 + idx] = 0.f;
    for (int idx = t0; idx < BB * DD; idx += stride)
        out[idx] = y0[idx];
}

__global__ void __launch_bounds__(NTH, 1)
ode_kernel(const float* __restrict__ ts, const float* __restrict__ y0,
           const float* __restrict__ W0, const float* __restrict__ b0,
           const float* __restrict__ b1, const float* __restrict__ b2,
           float* __restrict__ out) {
    extern __shared__ float sm[];
    int tid = threadIdx.x;
    int r0 = blockIdx.x * MT;

    for (int idx = tid; idx < 64 * 256; idx += NTH) {
        int w = idx >> 6, d = idx & 63;
        sm[OFF_W0T + d * 256 + w] = W0[idx];
    }
    if (tid < 256) { sm[OFF_B0 + tid] = b0[tid]; sm[OFF_B1 + tid] = b1[tid]; }
    if (tid < 64)  sm[OFF_B2 + tid] = b2[tid];
    if (tid < 32)  sm[OFF_TS + tid] = ts[tid];
    for (int i = tid; i < MT * DD; i += NTH) {
        int d = i >> 4, m = i & 15;
        sm[OFF_Y + d * HP + m] = y0[(r0 + m) * DD + d];
    }
    __syncthreads();

    float* sY = sm + OFF_Y;

    for (int iv = 0; iv < TT - 1; ++iv) {
        float t0v = sm[OFF_TS + iv];
        float h   = 0.5f * (sm[OFF_TS + iv + 1] - t0v);
        for (int sub = 0; sub < 2; ++sub) {
            float tc = t0v + sub * h;
            for (int s = 0; s < 6; ++s) {
                const float* aIn = (s == 0) ? sY : (sm + OFF_YT);
                vf_eval(sm, s, h, tc + h * c_C6[s], aIn, tid);
            }
        }
        float* dst = out + (size_t)(iv + 1) * BB * DD + (size_t)r0 * DD;
        for (int i = tid; i < MT * DD; i += NTH) {
            int m = i >> 6, d = i & 63;
            dst[i] = sY[d * HP + m];
        }
    }
}

extern "C" void kernel_launch(void* const* d_in, const int* in_sizes, int n_in,
                              void* d_out, int out_size) {
    if (n_in < 8) return;
    const float* ts = (const float*)d_in[0];
    const float* y0 = (const float*)d_in[1];
    const float* W0 = (const float*)d_in[2];
    const float* b0 = (const float*)d_in[3];
    const float* W1 = (const float*)d_in[4];
    const float* b1 = (const float*)d_in[5];
    const float* W2 = (const float*)d_in[6];
    const float* b2 = (const float*)d_in[7];
    float* out = (float*)d_out;

    cudaFuncSetAttribute(ode_kernel, cudaFuncAttributeMaxDynamicSharedMemorySize, SMEM_BYTES);

    prep_kernel<<<256, 256>>>(W1, W2, y0, out);
    ode_kernel<<<NCTA, NTH, SMEM_BYTES>>>(ts, y0, W0, b0, b1, b2, out);
}